// round 5
// baseline (speedup 1.0000x reference)
#include <cuda_runtime.h>
#include <math.h>
#include <stdint.h>

#define NN 50000
#define NE 800000
#define DD 64
#define GG 512
#define CHUNK 512
#define NCHUNK ((NN + CHUNK - 1) / CHUNK)   // 98

// -------- scratch (device globals; no allocation allowed) --------
__device__ float g_bufA[NN * DD];
__device__ float g_bufB[NN * DD];
__device__ float g_agg[NN * DD];
__device__ int   g_cnt[NN];
__device__ int   g_rowptr[NN + 1];
__device__ int   g_cursor[NN];
__device__ int   g_csr[NE];
__device__ int   g_chunksum[NCHUNK];
__device__ float g_pool[GG * DD];
__device__ float g_pcnt[GG];

__device__ __forceinline__ const float* pick_in(int sel, const float* x) {
    return sel == 0 ? x : (sel == 1 ? g_bufA : g_bufB);
}

__device__ __forceinline__ uint32_t tf32_bits(float x) {
    uint32_t u;
    asm("cvt.rna.tf32.f32 %0, %1;" : "=r"(u) : "f"(x));
    return u;
}
__device__ __forceinline__ void mma_tf32(float c[4], const uint32_t a[4],
                                         const uint32_t b[2]) {
    asm volatile(
        "mma.sync.aligned.m16n8k8.row.col.f32.tf32.tf32.f32 "
        "{%0,%1,%2,%3}, {%4,%5,%6,%7}, {%8,%9}, {%0,%1,%2,%3};"
        : "+f"(c[0]), "+f"(c[1]), "+f"(c[2]), "+f"(c[3])
        : "r"(a[0]), "r"(a[1]), "r"(a[2]), "r"(a[3]), "r"(b[0]), "r"(b[1]));
}

// -------- CSR build --------
__global__ void k_zero() {
    int i = blockIdx.x * blockDim.x + threadIdx.x;
    if (i < NN) g_cnt[i] = 0;
    if (i < GG) g_pcnt[i] = 0.f;
    if (i < GG * DD) g_pool[i] = 0.f;
}

__global__ void k_count(const int* __restrict__ dst) {
    int e = blockIdx.x * blockDim.x + threadIdx.x;
    if (e < NE) atomicAdd(&g_cnt[dst[e]], 1);
}

__global__ void k_scan1() {
    __shared__ int s[CHUNK];
    int i = blockIdx.x * CHUNK + threadIdx.x;
    s[threadIdx.x] = (i < NN) ? g_cnt[i] : 0;
    __syncthreads();
    for (int off = CHUNK / 2; off > 0; off >>= 1) {
        if (threadIdx.x < off) s[threadIdx.x] += s[threadIdx.x + off];
        __syncthreads();
    }
    if (threadIdx.x == 0) g_chunksum[blockIdx.x] = s[0];
}

__global__ void k_scan2() {
    __shared__ int s[128];
    int i = threadIdx.x;
    int v = (i < NCHUNK) ? g_chunksum[i] : 0;
    s[i] = v;
    __syncthreads();
    for (int off = 1; off < 128; off <<= 1) {
        int t = (i >= off) ? s[i - off] : 0;
        __syncthreads();
        s[i] += t;
        __syncthreads();
    }
    if (i < NCHUNK) g_chunksum[i] = s[i] - v;
    if (i == 0) g_rowptr[NN] = NE;
}

__global__ void k_scan3(const int* __restrict__ batch) {
    __shared__ int s[CHUNK];
    int i = blockIdx.x * CHUNK + threadIdx.x;
    int v = (i < NN) ? g_cnt[i] : 0;
    s[threadIdx.x] = v;
    __syncthreads();
    for (int off = 1; off < CHUNK; off <<= 1) {
        int t = (threadIdx.x >= off) ? s[threadIdx.x - off] : 0;
        __syncthreads();
        s[threadIdx.x] += t;
        __syncthreads();
    }
    if (i < NN) {
        int excl = g_chunksum[blockIdx.x] + s[threadIdx.x] - v;
        g_rowptr[i] = excl;
        g_cursor[i] = excl;
        atomicAdd(&g_pcnt[batch[i]], 1.f);
    }
}

__global__ void k_fill(const int* __restrict__ src, const int* __restrict__ dst) {
    int e = blockIdx.x * blockDim.x + threadIdx.x;
    if (e < NE) {
        int pos = atomicAdd(&g_cursor[dst[e]], 1);
        g_csr[pos] = src[e];
    }
}

// -------- per-layer edge aggregation --------
__global__ void k_agg(const float* __restrict__ x, int sel) {
    const float* h = pick_in(sel, x);
    int node = blockIdx.x * 16 + (threadIdx.x >> 4);
    int q = threadIdx.x & 15;
    if (node >= NN) return;
    int s0 = g_rowptr[node];
    int s1 = g_rowptr[node + 1];
    float4 a0 = make_float4(0.f, 0.f, 0.f, 0.f);
    float4 a1 = a0, a2 = a0, a3 = a0;
    int e = s0;
    int e4 = s0 + ((s1 - s0) & ~3);
    for (; e < e4; e += 4) {
        int i0 = __ldg(&g_csr[e + 0]);
        int i1 = __ldg(&g_csr[e + 1]);
        int i2 = __ldg(&g_csr[e + 2]);
        int i3 = __ldg(&g_csr[e + 3]);
        float4 v0 = __ldg((const float4*)&h[i0 * DD + q * 4]);
        float4 v1 = __ldg((const float4*)&h[i1 * DD + q * 4]);
        float4 v2 = __ldg((const float4*)&h[i2 * DD + q * 4]);
        float4 v3 = __ldg((const float4*)&h[i3 * DD + q * 4]);
        a0.x += v0.x; a0.y += v0.y; a0.z += v0.z; a0.w += v0.w;
        a1.x += v1.x; a1.y += v1.y; a1.z += v1.z; a1.w += v1.w;
        a2.x += v2.x; a2.y += v2.y; a2.z += v2.z; a2.w += v2.w;
        a3.x += v3.x; a3.y += v3.y; a3.z += v3.z; a3.w += v3.w;
    }
    for (; e < s1; e++) {
        int i0 = __ldg(&g_csr[e]);
        float4 v0 = __ldg((const float4*)&h[i0 * DD + q * 4]);
        a0.x += v0.x; a0.y += v0.y; a0.z += v0.z; a0.w += v0.w;
    }
    float4 r;
    r.x = (a0.x + a1.x) + (a2.x + a3.x);
    r.y = (a0.y + a1.y) + (a2.y + a3.y);
    r.z = (a0.z + a1.z) + (a2.z + a3.z);
    r.w = (a0.w + a1.w) + (a2.w + a3.w);
    *(float4*)&g_agg[node * DD + q * 4] = r;
}

// ========== fused layer GEMM via base-PTX mma.sync (tf32 x3 split) ==========
// D[128,64] = [agg|h][128,128] @ [Wrel|Wroot]^T
// A kept fp32 in smem (hi/lo split at frag load); B pre-split hi/lo in smem.
#define SA 132
#define SB 72
#define SMEM_A_BYTES (128 * SA * 4)          // 67584
#define SMEM_B_BYTES (128 * SB * 4)          // 36864
#define SMEM_DYN (SMEM_A_BYTES + 2 * SMEM_B_BYTES)

__global__ void __launch_bounds__(256, 1)
k_gemm_mma(const float* __restrict__ x, int insel, int outsel,
           const float* __restrict__ wrel,
           const float* __restrict__ wroot,
           const float* __restrict__ brel,
           int residual, int dopool, const int* __restrict__ batch) {
    const float* hin = pick_in(insel, x);
    float* hout = (outsel == 1) ? g_bufA : g_bufB;

    extern __shared__ char dynsm[];
    float*    As  = (float*)dynsm;
    uint32_t* Bhu = (uint32_t*)(dynsm + SMEM_A_BYTES);
    uint32_t* Blu = (uint32_t*)(dynsm + SMEM_A_BYTES + SMEM_B_BYTES);

    int tid = threadIdx.x;
    int wid = tid >> 5;
    int lid = tid & 31;
    int g = lid >> 2;          // 0..7
    int t = lid & 3;           // 0..3
    int m0 = blockIdx.x * 128;
    int mw = wid * 16;

    // ---- stage A = [agg | hin] as fp32, row-major stride SA ----
#pragma unroll
    for (int i = 0; i < 16; i++) {
        int idx = i * 256 + tid;          // 0..4095
        int m = idx >> 5;
        int k = (idx & 31) << 2;
        float4 v = make_float4(0.f, 0.f, 0.f, 0.f);
        int gm = m0 + m;
        if (gm < NN) {
            const float* sp = (k < 64) ? &g_agg[gm * DD + k]
                                       : &hin[gm * DD + (k - 64)];
            v = *(const float4*)sp;
        }
        *(float4*)&As[m * SA + k] = v;
    }
    // ---- stage B = [Wrel | Wroot]^T split hi/lo: B[k][n] = W[n][k] ----
#pragma unroll
    for (int i = 0; i < 8; i++) {
        int idx = i * 256 + tid;          // 0..2047
        int n = idx >> 5;
        int k = (idx & 31) << 2;
        const float* sp = (k < 64) ? &wrel[n * DD + k] : &wroot[n * DD + (k - 64)];
        float4 v = *(const float4*)sp;
        float vv[4] = {v.x, v.y, v.z, v.w};
#pragma unroll
        for (int j = 0; j < 4; j++) {
            uint32_t hb = tf32_bits(vv[j]);
            float hf = __uint_as_float(hb);
            Bhu[(k + j) * SB + n] = hb;
            Blu[(k + j) * SB + n] = tf32_bits(vv[j] - hf);
        }
    }
    __syncthreads();

    // ---- mma mainloop ----
    float acc[8][4];
#pragma unroll
    for (int nf = 0; nf < 8; nf++)
#pragma unroll
        for (int c = 0; c < 4; c++) acc[nf][c] = 0.f;

#pragma unroll 4
    for (int ks = 0; ks < 16; ks++) {
        int k0 = ks * 8;
        float av[4];
        av[0] = As[(mw + g) * SA + k0 + t];
        av[1] = As[(mw + g + 8) * SA + k0 + t];
        av[2] = As[(mw + g) * SA + k0 + t + 4];
        av[3] = As[(mw + g + 8) * SA + k0 + t + 4];
        uint32_t ahi[4], alo[4];
#pragma unroll
        for (int j = 0; j < 4; j++) {
            ahi[j] = tf32_bits(av[j]);
            alo[j] = tf32_bits(av[j] - __uint_as_float(ahi[j]));
        }
#pragma unroll
        for (int nf = 0; nf < 8; nf++) {
            uint32_t bh[2], bl[2];
            int nn = nf * 8 + g;
            bh[0] = Bhu[(k0 + t) * SB + nn];
            bh[1] = Bhu[(k0 + t + 4) * SB + nn];
            bl[0] = Blu[(k0 + t) * SB + nn];
            bl[1] = Blu[(k0 + t + 4) * SB + nn];
            mma_tf32(acc[nf], ahi, bh);
            mma_tf32(acc[nf], alo, bh);
            mma_tf32(acc[nf], ahi, bl);
        }
    }

    // ---- epilogue: bias + residual + relu + (pool | store) ----
    int r0 = m0 + mw + g;
    int r1 = r0 + 8;
#pragma unroll
    for (int nf = 0; nf < 8; nf++) {
        int col = nf * 8 + t * 2;
        float b0 = __ldg(&brel[col]);
        float b1 = __ldg(&brel[col + 1]);
#pragma unroll
        for (int half = 0; half < 2; half++) {
            int m = half ? r1 : r0;
            if (m >= NN) continue;
            float v0 = acc[nf][half * 2 + 0] + b0;
            float v1 = acc[nf][half * 2 + 1] + b1;
            if (residual) {
                float2 h2 = *(const float2*)&hin[m * DD + col];
                v0 += h2.x; v1 += h2.y;
            }
            v0 = fmaxf(v0, 0.f);
            v1 = fmaxf(v1, 0.f);
            if (dopool) {
                int b = __ldg(&batch[m]);
                atomicAdd(&g_pool[b * DD + col + 0], v0);
                atomicAdd(&g_pool[b * DD + col + 1], v1);
            } else {
                *(float2*)&hout[m * DD + col] = make_float2(v0, v1);
            }
        }
    }
}

// -------- final linear + softmax --------
__global__ void k_final(const float* __restrict__ lin_w,
                        const float* __restrict__ lin_b,
                        float* __restrict__ out) {
    __shared__ float sw[64 * 65];
    __shared__ float p[64];
    __shared__ float red[64];
    int g = blockIdx.x;
    int j = threadIdx.x;

    for (int r = 0; r < 64; r++) sw[j * 65 + r] = lin_w[r * 64 + j];

    float cnt = fmaxf(g_pcnt[g], 1.f);
    p[j] = g_pool[g * DD + j] / cnt;
    __syncthreads();

    float acc = lin_b[j];
#pragma unroll
    for (int k = 0; k < 64; k++) acc += p[k] * sw[k * 65 + j];

    red[j] = acc;
    __syncthreads();
    for (int s = 32; s > 0; s >>= 1) {
        if (j < s) red[j] = fmaxf(red[j], red[j + s]);
        __syncthreads();
    }
    float mx = red[0];
    __syncthreads();
    float e = expf(acc - mx);
    red[j] = e;
    __syncthreads();
    for (int s = 32; s > 0; s >>= 1) {
        if (j < s) red[j] += red[j + s];
        __syncthreads();
    }
    out[g * DD + j] = e / red[0];
}

extern "C" void kernel_launch(void* const* d_in, const int* in_sizes, int n_in,
                              void* d_out, int out_size) {
    const float* x      = (const float*)d_in[0];
    const int*   ei     = (const int*)d_in[1];
    const int*   batch  = (const int*)d_in[2];
    const float* rel_w  = (const float*)d_in[3];
    const float* rel_b  = (const float*)d_in[4];
    const float* root_w = (const float*)d_in[5];
    const float* lin_w  = (const float*)d_in[6];
    const float* lin_b  = (const float*)d_in[7];
    float* out = (float*)d_out;

    cudaFuncSetAttribute(k_gemm_mma, cudaFuncAttributeMaxDynamicSharedMemorySize,
                         SMEM_DYN);

    const int* src = ei;
    const int* dst = ei + NE;

    k_zero<<<(NN + 255) / 256, 256>>>();
    k_count<<<(NE + 255) / 256, 256>>>(dst);
    k_scan1<<<NCHUNK, CHUNK>>>();
    k_scan2<<<1, 128>>>();
    k_scan3<<<NCHUNK, CHUNK>>>(batch);
    k_fill<<<(NE + 255) / 256, 256>>>(src, dst);

    int insel = 0;
    for (int l = 0; l < 5; l++) {
        int outsel = (insel == 1) ? 2 : 1;
        k_agg<<<(NN + 15) / 16, 256>>>(x, insel);
        k_gemm_mma<<<(NN + 127) / 128, 256, SMEM_DYN>>>(
            x, insel, outsel,
            rel_w + l * DD * DD,
            root_w + l * DD * DD,
            rel_b + l * DD,
            (l >= 3) ? 1 : 0,
            (l == 4) ? 1 : 0,
            batch);
        insel = outsel;
    }

    k_final<<<GG, DD>>>(lin_w, lin_b, out);
}

// round 6
// speedup vs baseline: 1.5116x; 1.5116x over previous
#include <cuda_runtime.h>
#include <cuda_fp16.h>
#include <math.h>
#include <stdint.h>

#define NN 50000
#define NE 800000
#define DD 64
#define GG 512
#define CHUNK 512
#define NCHUNK ((NN + CHUNK - 1) / CHUNK)   // 98

// -------- scratch (device globals; no allocation allowed) --------
__device__ float g_bufA[NN * DD];
__device__ float g_bufB[NN * DD];
__device__ int   g_cnt[NN];
__device__ int   g_rowptr[NN + 1];
__device__ int   g_cursor[NN];
__device__ int   g_csr[NE];
__device__ int   g_chunksum[NCHUNK];
__device__ float g_pool[GG * DD];
__device__ float g_pcnt[GG];

__device__ __forceinline__ const float* pick_in(int sel, const float* x) {
    return sel == 0 ? x : (sel == 1 ? g_bufA : g_bufB);
}

// pack two floats into f16x2 hi and lo (split: x = hi + lo, err ~2^-22)
__device__ __forceinline__ void split2(float x, float y,
                                       uint32_t& hi, uint32_t& lo) {
    __half hx = __float2half_rn(x), hy = __float2half_rn(y);
    __half lx = __float2half_rn(x - __half2float(hx));
    __half ly = __float2half_rn(y - __half2float(hy));
    hi = (uint32_t)__half_as_ushort(hx) | ((uint32_t)__half_as_ushort(hy) << 16);
    lo = (uint32_t)__half_as_ushort(lx) | ((uint32_t)__half_as_ushort(ly) << 16);
}

__device__ __forceinline__ void mma_f16(float c[4], const uint32_t a[4],
                                        const uint32_t b[2]) {
    asm volatile(
        "mma.sync.aligned.m16n8k16.row.col.f32.f16.f16.f32 "
        "{%0,%1,%2,%3}, {%4,%5,%6,%7}, {%8,%9}, {%0,%1,%2,%3};"
        : "+f"(c[0]), "+f"(c[1]), "+f"(c[2]), "+f"(c[3])
        : "r"(a[0]), "r"(a[1]), "r"(a[2]), "r"(a[3]), "r"(b[0]), "r"(b[1]));
}

// -------- CSR build --------
__global__ void k_zero() {
    int i = blockIdx.x * blockDim.x + threadIdx.x;
    if (i < NN) g_cnt[i] = 0;
    if (i < GG) g_pcnt[i] = 0.f;
    if (i < GG * DD) g_pool[i] = 0.f;
}

__global__ void k_count(const int* __restrict__ dst) {
    int e = blockIdx.x * blockDim.x + threadIdx.x;
    if (e < NE) atomicAdd(&g_cnt[dst[e]], 1);
}

__global__ void k_scan1() {
    __shared__ int s[CHUNK];
    int i = blockIdx.x * CHUNK + threadIdx.x;
    s[threadIdx.x] = (i < NN) ? g_cnt[i] : 0;
    __syncthreads();
    for (int off = CHUNK / 2; off > 0; off >>= 1) {
        if (threadIdx.x < off) s[threadIdx.x] += s[threadIdx.x + off];
        __syncthreads();
    }
    if (threadIdx.x == 0) g_chunksum[blockIdx.x] = s[0];
}

__global__ void k_scan2() {
    __shared__ int s[128];
    int i = threadIdx.x;
    int v = (i < NCHUNK) ? g_chunksum[i] : 0;
    s[i] = v;
    __syncthreads();
    for (int off = 1; off < 128; off <<= 1) {
        int t = (i >= off) ? s[i - off] : 0;
        __syncthreads();
        s[i] += t;
        __syncthreads();
    }
    if (i < NCHUNK) g_chunksum[i] = s[i] - v;
    if (i == 0) g_rowptr[NN] = NE;
}

__global__ void k_scan3(const int* __restrict__ batch) {
    __shared__ int s[CHUNK];
    int i = blockIdx.x * CHUNK + threadIdx.x;
    int v = (i < NN) ? g_cnt[i] : 0;
    s[threadIdx.x] = v;
    __syncthreads();
    for (int off = 1; off < CHUNK; off <<= 1) {
        int t = (threadIdx.x >= off) ? s[threadIdx.x - off] : 0;
        __syncthreads();
        s[threadIdx.x] += t;
        __syncthreads();
    }
    if (i < NN) {
        int excl = g_chunksum[blockIdx.x] + s[threadIdx.x] - v;
        g_rowptr[i] = excl;
        g_cursor[i] = excl;
        atomicAdd(&g_pcnt[batch[i]], 1.f);
    }
}

__global__ void k_fill(const int* __restrict__ src, const int* __restrict__ dst) {
    int e = blockIdx.x * blockDim.x + threadIdx.x;
    if (e < NE) {
        int pos = atomicAdd(&g_cursor[dst[e]], 1);
        g_csr[pos] = src[e];
    }
}

// ========== fused layer: gather + GEMM (f16-split mma.sync) + epilogue ======
// Per block: 128 nodes. A[128,128] = [agg | h] (built in-kernel from CSR
// gather), B[64,128] = [Wrel | Wroot]. Both staged pre-split hi/lo f16x2.
// D = A@B^T via m16n8k16 HMMA, 3 products: Ah*Bh + Al*Bh + Ah*Bl.
#define ASTR 66                      // u32 stride per A row (64 pairs + pad)
#define A_U32 (128 * ASTR)           // 8448
#define B_U32 (64 * ASTR)            // 4224
#define SMEM_DYN ((2 * A_U32 + 2 * B_U32) * 4)   // 101376 bytes

__global__ void __launch_bounds__(256, 2)
k_layer(const float* __restrict__ x, int insel, int outsel,
        const float* __restrict__ wrel,
        const float* __restrict__ wroot,
        const float* __restrict__ brel,
        int residual, int dopool, const int* __restrict__ batch) {
    const float* hin = pick_in(insel, x);
    float* hout = (outsel == 1) ? g_bufA : g_bufB;

    extern __shared__ uint32_t sm[];
    uint32_t* Ah = sm;
    uint32_t* Al = sm + A_U32;
    uint32_t* Bh = sm + 2 * A_U32;
    uint32_t* Bl = sm + 2 * A_U32 + B_U32;

    int tid = threadIdx.x;
    int wid = tid >> 5;
    int lid = tid & 31;
    int g = lid >> 2;            // 0..7
    int t = lid & 3;             // 0..3
    int m0 = blockIdx.x * 128;

    // ---- stage B = [Wrel | Wroot], split hi/lo ----
#pragma unroll
    for (int i = 0; i < 8; i++) {
        int idx = i * 256 + tid;          // 0..2047 (u32 pair slots)
        int n = idx >> 5;                 // 0..63
        int c = idx & 31;                 // u32 col within half: k = 2c
        // first half (c as given) maps k<64 via wrel; second via (idx>>5)... 
        // use full 64 pair-cols: c2 in 0..63
        int c2 = (idx & 31) | 0;          // placeholder, recompute below
        (void)c2;
        // recompute: we need 64 rows x 64 pair-cols = 4096 slots, 2048 per pass
        int slot = idx;                   // pass 0 handles k-pairs 0..31
        int kp = slot & 31;               // pair col 0..31  (k = 2kp)
        float2 v0, v1;
        v0 = *(const float2*)&wrel[n * DD + 2 * kp];            // k in [0,64)
        v1 = *(const float2*)&wroot[n * DD + 2 * kp];           // k in [64,128)
        uint32_t h0, l0, h1, l1;
        split2(v0.x, v0.y, h0, l0);
        split2(v1.x, v1.y, h1, l1);
        Bh[n * ASTR + kp] = h0;      Bl[n * ASTR + kp] = l0;
        Bh[n * ASTR + 32 + kp] = h1; Bl[n * ASTR + 32 + kp] = l1;
    }

    // ---- gather + stage A = [agg | h], split hi/lo ----
    {
        int q = tid & 15;             // float4 slot within 64-float row
        int sub = tid >> 4;           // 0..15
#pragma unroll
        for (int it = 0; it < 8; it++) {
            int mloc = it * 16 + sub;           // 0..127
            int m = m0 + mloc;
            float4 a0 = make_float4(0.f, 0.f, 0.f, 0.f);
            float4 a1 = a0, a2 = a0, a3 = a0;
            float4 h4 = a0;
            if (m < NN) {
                int s0 = g_rowptr[m];
                int s1 = g_rowptr[m + 1];
                int e = s0;
                int e4 = s0 + ((s1 - s0) & ~3);
                for (; e < e4; e += 4) {
                    int i0 = __ldg(&g_csr[e + 0]);
                    int i1 = __ldg(&g_csr[e + 1]);
                    int i2 = __ldg(&g_csr[e + 2]);
                    int i3 = __ldg(&g_csr[e + 3]);
                    float4 v0 = __ldg((const float4*)&hin[i0 * DD + q * 4]);
                    float4 v1 = __ldg((const float4*)&hin[i1 * DD + q * 4]);
                    float4 v2 = __ldg((const float4*)&hin[i2 * DD + q * 4]);
                    float4 v3 = __ldg((const float4*)&hin[i3 * DD + q * 4]);
                    a0.x += v0.x; a0.y += v0.y; a0.z += v0.z; a0.w += v0.w;
                    a1.x += v1.x; a1.y += v1.y; a1.z += v1.z; a1.w += v1.w;
                    a2.x += v2.x; a2.y += v2.y; a2.z += v2.z; a2.w += v2.w;
                    a3.x += v3.x; a3.y += v3.y; a3.z += v3.z; a3.w += v3.w;
                }
                for (; e < s1; e++) {
                    int i0 = __ldg(&g_csr[e]);
                    float4 v0 = __ldg((const float4*)&hin[i0 * DD + q * 4]);
                    a0.x += v0.x; a0.y += v0.y; a0.z += v0.z; a0.w += v0.w;
                }
                h4 = __ldg((const float4*)&hin[m * DD + q * 4]);
            }
            float ax = (a0.x + a1.x) + (a2.x + a3.x);
            float ay = (a0.y + a1.y) + (a2.y + a3.y);
            float az = (a0.z + a1.z) + (a2.z + a3.z);
            float aw = (a0.w + a1.w) + (a2.w + a3.w);
            uint32_t h0, l0, h1, l1;
            // agg -> cols [0,64): pair cols 2q, 2q+1
            split2(ax, ay, h0, l0);
            split2(az, aw, h1, l1);
            Ah[mloc * ASTR + 2 * q] = h0;     Al[mloc * ASTR + 2 * q] = l0;
            Ah[mloc * ASTR + 2 * q + 1] = h1; Al[mloc * ASTR + 2 * q + 1] = l1;
            // h -> cols [64,128): pair cols 32+2q, 32+2q+1
            split2(h4.x, h4.y, h0, l0);
            split2(h4.z, h4.w, h1, l1);
            Ah[mloc * ASTR + 32 + 2 * q] = h0;     Al[mloc * ASTR + 32 + 2 * q] = l0;
            Ah[mloc * ASTR + 32 + 2 * q + 1] = h1; Al[mloc * ASTR + 32 + 2 * q + 1] = l1;
        }
    }
    __syncthreads();

    // ---- mma mainloop: warp wid owns rows [wid*16, wid*16+16) ----
    float acc[8][4];
#pragma unroll
    for (int nf = 0; nf < 8; nf++)
#pragma unroll
        for (int c = 0; c < 4; c++) acc[nf][c] = 0.f;

    int ar0 = (wid * 16 + g) * ASTR;
    int ar1 = (wid * 16 + g + 8) * ASTR;

#pragma unroll
    for (int ks = 0; ks < 8; ks++) {
        int kc = ks * 8;
        uint32_t ah[4], al[4];
        ah[0] = Ah[ar0 + kc + t];
        ah[1] = Ah[ar1 + kc + t];
        ah[2] = Ah[ar0 + kc + t + 4];
        ah[3] = Ah[ar1 + kc + t + 4];
        al[0] = Al[ar0 + kc + t];
        al[1] = Al[ar1 + kc + t];
        al[2] = Al[ar0 + kc + t + 4];
        al[3] = Al[ar1 + kc + t + 4];
#pragma unroll
        for (int nf = 0; nf < 8; nf++) {
            int nb = (nf * 8 + g) * ASTR + kc;
            uint32_t bh[2], bl[2];
            bh[0] = Bh[nb + t];
            bh[1] = Bh[nb + t + 4];
            bl[0] = Bl[nb + t];
            bl[1] = Bl[nb + t + 4];
            mma_f16(acc[nf], ah, bh);
            mma_f16(acc[nf], al, bh);
            mma_f16(acc[nf], ah, bl);
        }
    }

    // ---- epilogue: bias + residual + relu + (pool | store) ----
    int r0 = m0 + wid * 16 + g;
    int r1 = r0 + 8;
#pragma unroll
    for (int nf = 0; nf < 8; nf++) {
        int col = nf * 8 + t * 2;
        float b0 = __ldg(&brel[col]);
        float b1 = __ldg(&brel[col + 1]);
#pragma unroll
        for (int half = 0; half < 2; half++) {
            int m = half ? r1 : r0;
            if (m >= NN) continue;
            float v0 = acc[nf][half * 2 + 0] + b0;
            float v1 = acc[nf][half * 2 + 1] + b1;
            if (residual) {
                float2 h2 = *(const float2*)&hin[m * DD + col];
                v0 += h2.x; v1 += h2.y;
            }
            v0 = fmaxf(v0, 0.f);
            v1 = fmaxf(v1, 0.f);
            if (dopool) {
                int b = __ldg(&batch[m]);
                atomicAdd(&g_pool[b * DD + col + 0], v0);
                atomicAdd(&g_pool[b * DD + col + 1], v1);
            } else {
                *(float2*)&hout[m * DD + col] = make_float2(v0, v1);
            }
        }
    }
}

// -------- final linear + softmax --------
__global__ void k_final(const float* __restrict__ lin_w,
                        const float* __restrict__ lin_b,
                        float* __restrict__ out) {
    __shared__ float sw[64 * 65];
    __shared__ float p[64];
    __shared__ float red[64];
    int g = blockIdx.x;
    int j = threadIdx.x;

    for (int r = 0; r < 64; r++) sw[j * 65 + r] = lin_w[r * 64 + j];

    float cnt = fmaxf(g_pcnt[g], 1.f);
    p[j] = g_pool[g * DD + j] / cnt;
    __syncthreads();

    float acc = lin_b[j];
#pragma unroll
    for (int k = 0; k < 64; k++) acc += p[k] * sw[k * 65 + j];

    red[j] = acc;
    __syncthreads();
    for (int s = 32; s > 0; s >>= 1) {
        if (j < s) red[j] = fmaxf(red[j], red[j + s]);
        __syncthreads();
    }
    float mx = red[0];
    __syncthreads();
    float e = expf(acc - mx);
    red[j] = e;
    __syncthreads();
    for (int s = 32; s > 0; s >>= 1) {
        if (j < s) red[j] += red[j + s];
        __syncthreads();
    }
    out[g * DD + j] = e / red[0];
}

extern "C" void kernel_launch(void* const* d_in, const int* in_sizes, int n_in,
                              void* d_out, int out_size) {
    const float* x      = (const float*)d_in[0];
    const int*   ei     = (const int*)d_in[1];
    const int*   batch  = (const int*)d_in[2];
    const float* rel_w  = (const float*)d_in[3];
    const float* rel_b  = (const float*)d_in[4];
    const float* root_w = (const float*)d_in[5];
    const float* lin_w  = (const float*)d_in[6];
    const float* lin_b  = (const float*)d_in[7];
    float* out = (float*)d_out;

    cudaFuncSetAttribute(k_layer, cudaFuncAttributeMaxDynamicSharedMemorySize,
                         SMEM_DYN);

    const int* src = ei;
    const int* dst = ei + NE;

    k_zero<<<(NN + 255) / 256, 256>>>();
    k_count<<<(NE + 255) / 256, 256>>>(dst);
    k_scan1<<<NCHUNK, CHUNK>>>();
    k_scan2<<<1, 128>>>();
    k_scan3<<<NCHUNK, CHUNK>>>(batch);
    k_fill<<<(NE + 255) / 256, 256>>>(src, dst);

    int insel = 0;
    for (int l = 0; l < 5; l++) {
        int outsel = (insel == 1) ? 2 : 1;
        k_layer<<<(NN + 127) / 128, 256, SMEM_DYN>>>(
            x, insel, outsel,
            rel_w + l * DD * DD,
            root_w + l * DD * DD,
            rel_b + l * DD,
            (l >= 3) ? 1 : 0,
            (l == 4) ? 1 : 0,
            batch);
        insel = outsel;
    }

    k_final<<<GG, DD>>>(lin_w, lin_b, out);
}

// round 7
// speedup vs baseline: 1.5259x; 1.0095x over previous
#include <cuda_runtime.h>
#include <cuda_fp16.h>
#include <math.h>
#include <stdint.h>

#define NN 50000
#define NE 800000
#define DD 64
#define GG 512
#define CHUNK 512
#define NCHUNK ((NN + CHUNK - 1) / CHUNK)   // 98

// -------- scratch (device globals; no allocation allowed) --------
__device__ float g_bufA[NN * DD];
__device__ float g_bufB[NN * DD];
__device__ int   g_cnt[NN];
__device__ int   g_rowptr[NN + 1];
__device__ int   g_cursor[NN];
__device__ int   g_csr[NE];
__device__ int   g_chunksum[NCHUNK];
__device__ float g_pool[GG * DD];
__device__ float g_pcnt[GG];

__device__ __forceinline__ const float* pick_in(int sel, const float* x) {
    return sel == 0 ? x : (sel == 1 ? g_bufA : g_bufB);
}

// pack two floats into f16x2 hi and lo (split: x = hi + lo, err ~2^-22)
__device__ __forceinline__ void split2(float x, float y,
                                       uint32_t& hi, uint32_t& lo) {
    __half hx = __float2half_rn(x), hy = __float2half_rn(y);
    __half lx = __float2half_rn(x - __half2float(hx));
    __half ly = __float2half_rn(y - __half2float(hy));
    hi = (uint32_t)__half_as_ushort(hx) | ((uint32_t)__half_as_ushort(hy) << 16);
    lo = (uint32_t)__half_as_ushort(lx) | ((uint32_t)__half_as_ushort(ly) << 16);
}

__device__ __forceinline__ void mma_f16(float c[4], const uint32_t a[4],
                                        const uint32_t b[2]) {
    asm volatile(
        "mma.sync.aligned.m16n8k16.row.col.f32.f16.f16.f32 "
        "{%0,%1,%2,%3}, {%4,%5,%6,%7}, {%8,%9}, {%0,%1,%2,%3};"
        : "+f"(c[0]), "+f"(c[1]), "+f"(c[2]), "+f"(c[3])
        : "r"(a[0]), "r"(a[1]), "r"(a[2]), "r"(a[3]), "r"(b[0]), "r"(b[1]));
}

// -------- CSR build (5 launches) --------
__global__ void k_zero() {
    int i = blockIdx.x * blockDim.x + threadIdx.x;
    if (i < NN) g_cnt[i] = 0;
    if (i < GG) g_pcnt[i] = 0.f;
    if (i < GG * DD) g_pool[i] = 0.f;
}

__global__ void k_count(const int* __restrict__ dst) {
    int e = blockIdx.x * blockDim.x + threadIdx.x;
    if (e < NE) atomicAdd(&g_cnt[dst[e]], 1);
}

// per-chunk reduce
__global__ void k_scanA() {
    __shared__ int s[CHUNK];
    int i = blockIdx.x * CHUNK + threadIdx.x;
    s[threadIdx.x] = (i < NN) ? g_cnt[i] : 0;
    __syncthreads();
    for (int off = CHUNK / 2; off > 0; off >>= 1) {
        if (threadIdx.x < off) s[threadIdx.x] += s[threadIdx.x + off];
        __syncthreads();
    }
    if (threadIdx.x == 0) g_chunksum[blockIdx.x] = s[0];
}

// per-chunk scan with inline lookback over the 98 chunk sums
__global__ void k_scanB(const int* __restrict__ batch) {
    __shared__ int s[CHUNK];
    __shared__ int pre[128];
    int bid = blockIdx.x;
    int tx = threadIdx.x;
    int i = bid * CHUNK + tx;

    if (tx < 128) pre[tx] = (tx < bid) ? g_chunksum[tx] : 0;
    int v = (i < NN) ? g_cnt[i] : 0;
    s[tx] = v;
    __syncthreads();
    if (tx < 64) pre[tx] += pre[tx + 64];
    __syncthreads();
    if (tx < 32) {
        int a = pre[tx] + pre[tx + 32];
        for (int off = 16; off > 0; off >>= 1)
            a += __shfl_down_sync(0xFFFFFFFF, a, off);
        if (tx == 0) pre[0] = a;
    }
    for (int off = 1; off < CHUNK; off <<= 1) {
        int t = (tx >= off) ? s[tx - off] : 0;
        __syncthreads();
        s[tx] += t;
        __syncthreads();
    }
    if (i < NN) {
        int excl = pre[0] + s[tx] - v;
        g_rowptr[i] = excl;
        g_cursor[i] = excl;
        atomicAdd(&g_pcnt[batch[i]], 1.f);
    }
    if (bid == 0 && tx == 0) g_rowptr[NN] = NE;
}

__global__ void k_fill(const int* __restrict__ src, const int* __restrict__ dst) {
    int e = blockIdx.x * blockDim.x + threadIdx.x;
    if (e < NE) {
        int pos = atomicAdd(&g_cursor[dst[e]], 1);
        g_csr[pos] = src[e];
    }
}

// ========== fused layer: gather + GEMM (f16-split mma.sync) + epilogue ======
// Per block: 128 nodes. A[128,128] = [agg | h] from CSR gather, B = [Wrel|Wroot].
// ASTR=68 -> frag LDS bank = (4g+t)%32, bijective over warp: conflict-free.
#define ASTR 68
#define A_U32 (128 * ASTR)           // 8704
#define B_U32 (64 * ASTR)            // 4352
#define SMEM_DYN ((2 * A_U32 + 2 * B_U32) * 4)   // 104448 bytes

__global__ void __launch_bounds__(256, 2)
k_layer(const float* __restrict__ x, int insel, int outsel,
        const float* __restrict__ wrel,
        const float* __restrict__ wroot,
        const float* __restrict__ brel,
        int residual, int dopool, const int* __restrict__ batch) {
    const float* hin = pick_in(insel, x);
    float* hout = (outsel == 1) ? g_bufA : g_bufB;

    extern __shared__ uint32_t sm[];
    uint32_t* Ah = sm;
    uint32_t* Al = sm + A_U32;
    uint32_t* Bh = sm + 2 * A_U32;
    uint32_t* Bl = sm + 2 * A_U32 + B_U32;

    int tid = threadIdx.x;
    int wid = tid >> 5;
    int lid = tid & 31;
    int g = lid >> 2;            // 0..7
    int t = lid & 3;             // 0..3
    int m0 = blockIdx.x * 128;

    // ---- stage B = [Wrel | Wroot], split hi/lo ----
#pragma unroll
    for (int i = 0; i < 8; i++) {
        int idx = i * 256 + tid;          // 0..2047
        int n = idx >> 5;                 // 0..63
        int kp = idx & 31;                // pair col 0..31  (k = 2kp)
        float2 v0 = *(const float2*)&wrel[n * DD + 2 * kp];
        float2 v1 = *(const float2*)&wroot[n * DD + 2 * kp];
        uint32_t h0, l0, h1, l1;
        split2(v0.x, v0.y, h0, l0);
        split2(v1.x, v1.y, h1, l1);
        Bh[n * ASTR + kp] = h0;      Bl[n * ASTR + kp] = l0;
        Bh[n * ASTR + 32 + kp] = h1; Bl[n * ASTR + 32 + kp] = l1;
    }

    // ---- gather + stage A = [agg | h], split hi/lo (8-deep MLP) ----
    {
        int q = tid & 15;             // float4 slot within 64-float row
        int sub = tid >> 4;           // 0..15
#pragma unroll
        for (int it = 0; it < 8; it++) {
            int mloc = it * 16 + sub;           // 0..127
            int m = m0 + mloc;
            float4 a0 = make_float4(0.f, 0.f, 0.f, 0.f);
            float4 a1 = a0, a2 = a0, a3 = a0;
            float4 a4 = a0, a5 = a0, a6 = a0, a7 = a0;
            float4 h4 = a0;
            if (m < NN) {
                int s0 = g_rowptr[m];
                int s1 = g_rowptr[m + 1];
                int e = s0;
                int e8 = s0 + ((s1 - s0) & ~7);
                for (; e < e8; e += 8) {
                    int i0 = __ldg(&g_csr[e + 0]);
                    int i1 = __ldg(&g_csr[e + 1]);
                    int i2 = __ldg(&g_csr[e + 2]);
                    int i3 = __ldg(&g_csr[e + 3]);
                    int i4 = __ldg(&g_csr[e + 4]);
                    int i5 = __ldg(&g_csr[e + 5]);
                    int i6 = __ldg(&g_csr[e + 6]);
                    int i7 = __ldg(&g_csr[e + 7]);
                    float4 v0 = __ldg((const float4*)&hin[i0 * DD + q * 4]);
                    float4 v1 = __ldg((const float4*)&hin[i1 * DD + q * 4]);
                    float4 v2 = __ldg((const float4*)&hin[i2 * DD + q * 4]);
                    float4 v3 = __ldg((const float4*)&hin[i3 * DD + q * 4]);
                    float4 v4 = __ldg((const float4*)&hin[i4 * DD + q * 4]);
                    float4 v5 = __ldg((const float4*)&hin[i5 * DD + q * 4]);
                    float4 v6 = __ldg((const float4*)&hin[i6 * DD + q * 4]);
                    float4 v7 = __ldg((const float4*)&hin[i7 * DD + q * 4]);
                    a0.x += v0.x; a0.y += v0.y; a0.z += v0.z; a0.w += v0.w;
                    a1.x += v1.x; a1.y += v1.y; a1.z += v1.z; a1.w += v1.w;
                    a2.x += v2.x; a2.y += v2.y; a2.z += v2.z; a2.w += v2.w;
                    a3.x += v3.x; a3.y += v3.y; a3.z += v3.z; a3.w += v3.w;
                    a4.x += v4.x; a4.y += v4.y; a4.z += v4.z; a4.w += v4.w;
                    a5.x += v5.x; a5.y += v5.y; a5.z += v5.z; a5.w += v5.w;
                    a6.x += v6.x; a6.y += v6.y; a6.z += v6.z; a6.w += v6.w;
                    a7.x += v7.x; a7.y += v7.y; a7.z += v7.z; a7.w += v7.w;
                }
                for (; e < s1; e++) {
                    int i0 = __ldg(&g_csr[e]);
                    float4 v0 = __ldg((const float4*)&hin[i0 * DD + q * 4]);
                    a0.x += v0.x; a0.y += v0.y; a0.z += v0.z; a0.w += v0.w;
                }
                h4 = __ldg((const float4*)&hin[m * DD + q * 4]);
            }
            float ax = ((a0.x + a1.x) + (a2.x + a3.x)) + ((a4.x + a5.x) + (a6.x + a7.x));
            float ay = ((a0.y + a1.y) + (a2.y + a3.y)) + ((a4.y + a5.y) + (a6.y + a7.y));
            float az = ((a0.z + a1.z) + (a2.z + a3.z)) + ((a4.z + a5.z) + (a6.z + a7.z));
            float aw = ((a0.w + a1.w) + (a2.w + a3.w)) + ((a4.w + a5.w) + (a6.w + a7.w));
            uint32_t h0, l0, h1, l1;
            split2(ax, ay, h0, l0);
            split2(az, aw, h1, l1);
            Ah[mloc * ASTR + 2 * q] = h0;     Al[mloc * ASTR + 2 * q] = l0;
            Ah[mloc * ASTR + 2 * q + 1] = h1; Al[mloc * ASTR + 2 * q + 1] = l1;
            split2(h4.x, h4.y, h0, l0);
            split2(h4.z, h4.w, h1, l1);
            Ah[mloc * ASTR + 32 + 2 * q] = h0;     Al[mloc * ASTR + 32 + 2 * q] = l0;
            Ah[mloc * ASTR + 32 + 2 * q + 1] = h1; Al[mloc * ASTR + 32 + 2 * q + 1] = l1;
        }
    }
    __syncthreads();

    // ---- mma mainloop: warp wid owns rows [wid*16, wid*16+16) ----
    float acc[8][4];
#pragma unroll
    for (int nf = 0; nf < 8; nf++)
#pragma unroll
        for (int c = 0; c < 4; c++) acc[nf][c] = 0.f;

    int ar0 = (wid * 16 + g) * ASTR;
    int ar1 = (wid * 16 + g + 8) * ASTR;

#pragma unroll
    for (int ks = 0; ks < 8; ks++) {
        int kc = ks * 8;
        uint32_t ah[4], al[4];
        ah[0] = Ah[ar0 + kc + t];
        ah[1] = Ah[ar1 + kc + t];
        ah[2] = Ah[ar0 + kc + t + 4];
        ah[3] = Ah[ar1 + kc + t + 4];
        al[0] = Al[ar0 + kc + t];
        al[1] = Al[ar1 + kc + t];
        al[2] = Al[ar0 + kc + t + 4];
        al[3] = Al[ar1 + kc + t + 4];
#pragma unroll
        for (int nf = 0; nf < 8; nf++) {
            int nb = (nf * 8 + g) * ASTR + kc;
            uint32_t bh[2], bl[2];
            bh[0] = Bh[nb + t];
            bh[1] = Bh[nb + t + 4];
            bl[0] = Bl[nb + t];
            bl[1] = Bl[nb + t + 4];
            mma_f16(acc[nf], ah, bh);
            mma_f16(acc[nf], al, bh);
            mma_f16(acc[nf], ah, bl);
        }
    }

    // ---- epilogue: bias + residual + relu + (pool | store) ----
    int r0 = m0 + wid * 16 + g;
    int r1 = r0 + 8;
#pragma unroll
    for (int nf = 0; nf < 8; nf++) {
        int col = nf * 8 + t * 2;
        float b0 = __ldg(&brel[col]);
        float b1 = __ldg(&brel[col + 1]);
#pragma unroll
        for (int half = 0; half < 2; half++) {
            int m = half ? r1 : r0;
            if (m >= NN) continue;
            float v0 = acc[nf][half * 2 + 0] + b0;
            float v1 = acc[nf][half * 2 + 1] + b1;
            if (residual) {
                float2 h2 = *(const float2*)&hin[m * DD + col];
                v0 += h2.x; v1 += h2.y;
            }
            v0 = fmaxf(v0, 0.f);
            v1 = fmaxf(v1, 0.f);
            if (dopool) {
                int b = __ldg(&batch[m]);
                atomicAdd(&g_pool[b * DD + col + 0], v0);
                atomicAdd(&g_pool[b * DD + col + 1], v1);
            } else {
                *(float2*)&hout[m * DD + col] = make_float2(v0, v1);
            }
        }
    }
}

// -------- final linear + softmax --------
__global__ void k_final(const float* __restrict__ lin_w,
                        const float* __restrict__ lin_b,
                        float* __restrict__ out) {
    __shared__ float sw[64 * 65];
    __shared__ float p[64];
    __shared__ float red[64];
    int g = blockIdx.x;
    int j = threadIdx.x;

    for (int r = 0; r < 64; r++) sw[j * 65 + r] = lin_w[r * 64 + j];

    float cnt = fmaxf(g_pcnt[g], 1.f);
    p[j] = g_pool[g * DD + j] / cnt;
    __syncthreads();

    float acc = lin_b[j];
#pragma unroll
    for (int k = 0; k < 64; k++) acc += p[k] * sw[k * 65 + j];

    red[j] = acc;
    __syncthreads();
    for (int s = 32; s > 0; s >>= 1) {
        if (j < s) red[j] = fmaxf(red[j], red[j + s]);
        __syncthreads();
    }
    float mx = red[0];
    __syncthreads();
    float e = expf(acc - mx);
    red[j] = e;
    __syncthreads();
    for (int s = 32; s > 0; s >>= 1) {
        if (j < s) red[j] += red[j + s];
        __syncthreads();
    }
    out[g * DD + j] = e / red[0];
}

extern "C" void kernel_launch(void* const* d_in, const int* in_sizes, int n_in,
                              void* d_out, int out_size) {
    const float* x      = (const float*)d_in[0];
    const int*   ei     = (const int*)d_in[1];
    const int*   batch  = (const int*)d_in[2];
    const float* rel_w  = (const float*)d_in[3];
    const float* rel_b  = (const float*)d_in[4];
    const float* root_w = (const float*)d_in[5];
    const float* lin_w  = (const float*)d_in[6];
    const float* lin_b  = (const float*)d_in[7];
    float* out = (float*)d_out;

    cudaFuncSetAttribute(k_layer, cudaFuncAttributeMaxDynamicSharedMemorySize,
                         SMEM_DYN);

    const int* src = ei;
    const int* dst = ei + NE;

    k_zero<<<(NN + 255) / 256, 256>>>();
    k_count<<<(NE + 255) / 256, 256>>>(dst);
    k_scanA<<<NCHUNK, CHUNK>>>();
    k_scanB<<<NCHUNK, CHUNK>>>(batch);
    k_fill<<<(NE + 255) / 256, 256>>>(src, dst);

    int insel = 0;
    for (int l = 0; l < 5; l++) {
        int outsel = (insel == 1) ? 2 : 1;
        k_layer<<<(NN + 127) / 128, 256, SMEM_DYN>>>(
            x, insel, outsel,
            rel_w + l * DD * DD,
            root_w + l * DD * DD,
            rel_b + l * DD,
            (l >= 3) ? 1 : 0,
            (l == 4) ? 1 : 0,
            batch);
        insel = outsel;
    }

    k_final<<<GG, DD>>>(lin_w, lin_b, out);
}

// round 8
// speedup vs baseline: 2.2291x; 1.4608x over previous
#include <cuda_runtime.h>
#include <cuda_fp16.h>
#include <math.h>
#include <stdint.h>

#define NN 50000
#define NE 800000
#define DD 64
#define GG 512
#define CHUNK 512
#define NCHUNK ((NN + CHUNK - 1) / CHUNK)   // 98

// -------- scratch (device globals; no allocation allowed) --------
__device__ uint32_t g_hA[NN * 32];   // activations as f16x2 pairs
__device__ uint32_t g_hB[NN * 32];
__device__ int   g_cnt[NN];
__device__ int   g_rowptr[NN + 1];
__device__ int   g_cursor[NN];
__device__ int   g_csr[NE];
__device__ int   g_chunksum[NCHUNK];
__device__ float g_pool[GG * DD];
__device__ float g_pcnt[GG];

__device__ __forceinline__ uint32_t pack2(float x, float y) {
    __half2 h = __floats2half2_rn(x, y);
    return *(uint32_t*)&h;
}
__device__ __forceinline__ float2 unpack2(uint32_t u) {
    return __half22float2(*(const __half2*)&u);
}
// split two floats into f16x2 hi and lo (x = hi + lo, err ~2^-22)
__device__ __forceinline__ void split2(float x, float y,
                                       uint32_t& hi, uint32_t& lo) {
    __half hx = __float2half_rn(x), hy = __float2half_rn(y);
    __half lx = __float2half_rn(x - __half2float(hx));
    __half ly = __float2half_rn(y - __half2float(hy));
    hi = (uint32_t)__half_as_ushort(hx) | ((uint32_t)__half_as_ushort(hy) << 16);
    lo = (uint32_t)__half_as_ushort(lx) | ((uint32_t)__half_as_ushort(ly) << 16);
}
__device__ __forceinline__ void mma_f16(float c[4], const uint32_t a[4],
                                        const uint32_t b[2]) {
    asm volatile(
        "mma.sync.aligned.m16n8k16.row.col.f32.f16.f16.f32 "
        "{%0,%1,%2,%3}, {%4,%5,%6,%7}, {%8,%9}, {%0,%1,%2,%3};"
        : "+f"(c[0]), "+f"(c[1]), "+f"(c[2]), "+f"(c[3])
        : "r"(a[0]), "r"(a[1]), "r"(a[2]), "r"(a[3]), "r"(b[0]), "r"(b[1]));
}

// -------- CSR build --------
__global__ void k_zero() {
    int i = blockIdx.x * blockDim.x + threadIdx.x;
    if (i < NN) g_cnt[i] = 0;
    if (i < GG) g_pcnt[i] = 0.f;
    if (i < GG * DD) g_pool[i] = 0.f;
}

__global__ void k_count(const int* __restrict__ dst) {
    int e = blockIdx.x * blockDim.x + threadIdx.x;
    if (e < NE) atomicAdd(&g_cnt[dst[e]], 1);
}

// per-chunk reduce (warp shuffles, 1 barrier)
__global__ void k_scanA() {
    __shared__ int wsum[16];
    int i = blockIdx.x * CHUNK + threadIdx.x;
    int lane = threadIdx.x & 31, w = threadIdx.x >> 5;
    int v = (i < NN) ? g_cnt[i] : 0;
    for (int off = 16; off > 0; off >>= 1)
        v += __shfl_down_sync(0xFFFFFFFF, v, off);
    if (lane == 0) wsum[w] = v;
    __syncthreads();
    if (w == 0) {
        int a = (lane < 16) ? wsum[lane] : 0;
        for (int off = 8; off > 0; off >>= 1)
            a += __shfl_down_sync(0xFFFFFFFF, a, off);
        if (lane == 0) g_chunksum[blockIdx.x] = a;
    }
}

// per-chunk exclusive scan + inline lookback (warp shuffles, 2 barriers)
__global__ void k_scanB(const int* __restrict__ batch) {
    __shared__ int wsum[16];
    __shared__ int s_pre;
    int bid = blockIdx.x, tx = threadIdx.x;
    int lane = tx & 31, w = tx >> 5;

    if (w == 0) {
        int a = 0;
        for (int j = lane; j < bid; j += 32) a += g_chunksum[j];
        for (int off = 16; off > 0; off >>= 1)
            a += __shfl_down_sync(0xFFFFFFFF, a, off);
        if (lane == 0) s_pre = a;
    }
    int i = bid * CHUNK + tx;
    int v = (i < NN) ? g_cnt[i] : 0;
    int sc = v;
    for (int off = 1; off < 32; off <<= 1) {
        int t = __shfl_up_sync(0xFFFFFFFF, sc, off);
        if (lane >= off) sc += t;
    }
    if (lane == 31) wsum[w] = sc;
    __syncthreads();
    if (w == 0) {
        int a = (lane < 16) ? wsum[lane] : 0;
        for (int off = 1; off < 16; off <<= 1) {
            int t = __shfl_up_sync(0xFFFFFFFF, a, off);
            if (lane >= off) a += t;
        }
        if (lane < 16) wsum[lane] = a;
    }
    __syncthreads();
    int excl = s_pre + ((w > 0) ? wsum[w - 1] : 0) + sc - v;
    if (i < NN) {
        g_rowptr[i] = excl;
        g_cursor[i] = excl;
        atomicAdd(&g_pcnt[batch[i]], 1.f);
    }
    if (bid == 0 && tx == 0) g_rowptr[NN] = NE;
}

__global__ void k_fill(const int* __restrict__ src, const int* __restrict__ dst) {
    int e = blockIdx.x * blockDim.x + threadIdx.x;
    if (e < NE) {
        int pos = atomicAdd(&g_cursor[dst[e]], 1);
        g_csr[pos] = src[e];
    }
}

// ========== fused layer: gather + GEMM (f16 mma, B split) + epilogue ========
// A[128,128] = [agg | h] single-f16; B = [Wrel|Wroot] hi/lo split.
// D = A*Bh + A*Bl (2 HMMA products). Activations live as f16x2 in g_hA/g_hB.
#define ASTR 68
#define A_U32 (128 * ASTR)           // 8704
#define B_U32 (64 * ASTR)            // 4352
#define SMEM_DYN ((A_U32 + 2 * B_U32) * 4)   // 69632 bytes

__global__ void __launch_bounds__(256, 3)
k_layer(const float* __restrict__ x, int insel, int outsel,
        const float* __restrict__ wrel,
        const float* __restrict__ wroot,
        const float* __restrict__ brel,
        int residual, int dopool, const int* __restrict__ batch) {
    const uint32_t* hinh = (insel == 1) ? g_hA : g_hB;
    uint32_t* hout = (outsel == 1) ? g_hA : g_hB;

    extern __shared__ uint32_t sm[];
    uint32_t* Ah = sm;
    uint32_t* Bh = sm + A_U32;
    uint32_t* Bl = sm + A_U32 + B_U32;

    int tid = threadIdx.x;
    int wid = tid >> 5;
    int lid = tid & 31;
    int g = lid >> 2;            // 0..7
    int t = lid & 3;             // 0..3
    int m0 = blockIdx.x * 128;

    // ---- stage B = [Wrel | Wroot], split hi/lo ----
#pragma unroll
    for (int i = 0; i < 8; i++) {
        int idx = i * 256 + tid;          // 0..2047
        int n = idx >> 5;                 // 0..63
        int kp = idx & 31;                // pair col (k = 2kp)
        float2 v0 = *(const float2*)&wrel[n * DD + 2 * kp];
        float2 v1 = *(const float2*)&wroot[n * DD + 2 * kp];
        uint32_t h0, l0, h1, l1;
        split2(v0.x, v0.y, h0, l0);
        split2(v1.x, v1.y, h1, l1);
        Bh[n * ASTR + kp] = h0;      Bl[n * ASTR + kp] = l0;
        Bh[n * ASTR + 32 + kp] = h1; Bl[n * ASTR + 32 + kp] = l1;
    }

    // ---- gather + stage A = [agg | h] (single f16) ----
    {
        int q = tid & 15;             // quad (4 floats / 2 pairs) within row
        int sub = tid >> 4;           // 0..15
#pragma unroll
        for (int it = 0; it < 8; it++) {
            int mloc = it * 16 + sub;           // 0..127
            int m = m0 + mloc;
            float ax = 0.f, ay = 0.f, az = 0.f, aw = 0.f;
            uint32_t hp0 = 0, hp1 = 0;
            if (m < NN) {
                int s0 = g_rowptr[m];
                int s1 = g_rowptr[m + 1];
                if (insel == 0) {
                    // layer 0: gather fp32 x
                    float4 a0 = make_float4(0.f, 0.f, 0.f, 0.f);
                    float4 a1 = a0, a2 = a0, a3 = a0;
                    int e = s0;
                    int e4 = s0 + ((s1 - s0) & ~3);
                    for (; e < e4; e += 4) {
                        int i0 = __ldg(&g_csr[e + 0]);
                        int i1 = __ldg(&g_csr[e + 1]);
                        int i2 = __ldg(&g_csr[e + 2]);
                        int i3 = __ldg(&g_csr[e + 3]);
                        float4 v0 = __ldg((const float4*)&x[i0 * DD + q * 4]);
                        float4 v1 = __ldg((const float4*)&x[i1 * DD + q * 4]);
                        float4 v2 = __ldg((const float4*)&x[i2 * DD + q * 4]);
                        float4 v3 = __ldg((const float4*)&x[i3 * DD + q * 4]);
                        a0.x += v0.x; a0.y += v0.y; a0.z += v0.z; a0.w += v0.w;
                        a1.x += v1.x; a1.y += v1.y; a1.z += v1.z; a1.w += v1.w;
                        a2.x += v2.x; a2.y += v2.y; a2.z += v2.z; a2.w += v2.w;
                        a3.x += v3.x; a3.y += v3.y; a3.z += v3.z; a3.w += v3.w;
                    }
                    for (; e < s1; e++) {
                        int i0 = __ldg(&g_csr[e]);
                        float4 v0 = __ldg((const float4*)&x[i0 * DD + q * 4]);
                        a0.x += v0.x; a0.y += v0.y; a0.z += v0.z; a0.w += v0.w;
                    }
                    ax = (a0.x + a1.x) + (a2.x + a3.x);
                    ay = (a0.y + a1.y) + (a2.y + a3.y);
                    az = (a0.z + a1.z) + (a2.z + a3.z);
                    aw = (a0.w + a1.w) + (a2.w + a3.w);
                    float4 h4 = __ldg((const float4*)&x[m * DD + q * 4]);
                    hp0 = pack2(h4.x, h4.y);
                    hp1 = pack2(h4.z, h4.w);
                } else {
                    // f16 layers: gather half2 pairs (8 bytes/lane/edge)
                    float x0 = 0.f, y0 = 0.f, z0 = 0.f, w0 = 0.f;
                    float x1 = 0.f, y1 = 0.f, z1 = 0.f, w1 = 0.f;
                    float x2 = 0.f, y2 = 0.f, z2 = 0.f, w2 = 0.f;
                    float x3 = 0.f, y3 = 0.f, z3 = 0.f, w3 = 0.f;
                    int e = s0;
                    int e4 = s0 + ((s1 - s0) & ~3);
                    for (; e < e4; e += 4) {
                        int i0 = __ldg(&g_csr[e + 0]);
                        int i1 = __ldg(&g_csr[e + 1]);
                        int i2 = __ldg(&g_csr[e + 2]);
                        int i3 = __ldg(&g_csr[e + 3]);
                        uint2 u0 = __ldg((const uint2*)&hinh[i0 * 32 + 2 * q]);
                        uint2 u1 = __ldg((const uint2*)&hinh[i1 * 32 + 2 * q]);
                        uint2 u2 = __ldg((const uint2*)&hinh[i2 * 32 + 2 * q]);
                        uint2 u3 = __ldg((const uint2*)&hinh[i3 * 32 + 2 * q]);
                        float2 f;
                        f = unpack2(u0.x); x0 += f.x; y0 += f.y;
                        f = unpack2(u0.y); z0 += f.x; w0 += f.y;
                        f = unpack2(u1.x); x1 += f.x; y1 += f.y;
                        f = unpack2(u1.y); z1 += f.x; w1 += f.y;
                        f = unpack2(u2.x); x2 += f.x; y2 += f.y;
                        f = unpack2(u2.y); z2 += f.x; w2 += f.y;
                        f = unpack2(u3.x); x3 += f.x; y3 += f.y;
                        f = unpack2(u3.y); z3 += f.x; w3 += f.y;
                    }
                    for (; e < s1; e++) {
                        int i0 = __ldg(&g_csr[e]);
                        uint2 u0 = __ldg((const uint2*)&hinh[i0 * 32 + 2 * q]);
                        float2 f;
                        f = unpack2(u0.x); x0 += f.x; y0 += f.y;
                        f = unpack2(u0.y); z0 += f.x; w0 += f.y;
                    }
                    ax = (x0 + x1) + (x2 + x3);
                    ay = (y0 + y1) + (y2 + y3);
                    az = (z0 + z1) + (z2 + z3);
                    aw = (w0 + w1) + (w2 + w3);
                    uint2 hu = __ldg((const uint2*)&hinh[m * 32 + 2 * q]);
                    hp0 = hu.x;
                    hp1 = hu.y;
                }
            }
            Ah[mloc * ASTR + 2 * q]     = pack2(ax, ay);
            Ah[mloc * ASTR + 2 * q + 1] = pack2(az, aw);
            Ah[mloc * ASTR + 32 + 2 * q]     = hp0;
            Ah[mloc * ASTR + 32 + 2 * q + 1] = hp1;
        }
    }
    __syncthreads();

    // ---- mma mainloop: warp wid owns rows [wid*16, wid*16+16) ----
    float acc[8][4];
#pragma unroll
    for (int nf = 0; nf < 8; nf++)
#pragma unroll
        for (int c = 0; c < 4; c++) acc[nf][c] = 0.f;

    int ar0 = (wid * 16 + g) * ASTR;
    int ar1 = (wid * 16 + g + 8) * ASTR;

#pragma unroll
    for (int ks = 0; ks < 8; ks++) {
        int kc = ks * 8;
        uint32_t ah[4];
        ah[0] = Ah[ar0 + kc + t];
        ah[1] = Ah[ar1 + kc + t];
        ah[2] = Ah[ar0 + kc + t + 4];
        ah[3] = Ah[ar1 + kc + t + 4];
#pragma unroll
        for (int nf = 0; nf < 8; nf++) {
            int nb = (nf * 8 + g) * ASTR + kc;
            uint32_t bh[2], bl[2];
            bh[0] = Bh[nb + t];
            bh[1] = Bh[nb + t + 4];
            bl[0] = Bl[nb + t];
            bl[1] = Bl[nb + t + 4];
            mma_f16(acc[nf], ah, bh);
            mma_f16(acc[nf], ah, bl);
        }
    }

    // ---- epilogue: bias + residual + relu + (pool | store f16) ----
    int r0 = m0 + wid * 16 + g;
    int r1 = r0 + 8;
#pragma unroll
    for (int nf = 0; nf < 8; nf++) {
        int col = nf * 8 + t * 2;
        float b0 = __ldg(&brel[col]);
        float b1 = __ldg(&brel[col + 1]);
#pragma unroll
        for (int half = 0; half < 2; half++) {
            int m = half ? r1 : r0;
            if (m >= NN) continue;
            float v0 = acc[nf][half * 2 + 0] + b0;
            float v1 = acc[nf][half * 2 + 1] + b1;
            if (residual) {
                float2 h2 = unpack2(hinh[m * 32 + (col >> 1)]);
                v0 += h2.x; v1 += h2.y;
            }
            v0 = fmaxf(v0, 0.f);
            v1 = fmaxf(v1, 0.f);
            if (dopool) {
                int b = __ldg(&batch[m]);
                atomicAdd(&g_pool[b * DD + col + 0], v0);
                atomicAdd(&g_pool[b * DD + col + 1], v1);
            } else {
                hout[m * 32 + (col >> 1)] = pack2(v0, v1);
            }
        }
    }
}

// -------- final linear + softmax --------
__global__ void k_final(const float* __restrict__ lin_w,
                        const float* __restrict__ lin_b,
                        float* __restrict__ out) {
    __shared__ float sw[64 * 65];
    __shared__ float p[64];
    __shared__ float red[64];
    int g = blockIdx.x;
    int j = threadIdx.x;

    for (int r = 0; r < 64; r++) sw[j * 65 + r] = lin_w[r * 64 + j];

    float cnt = fmaxf(g_pcnt[g], 1.f);
    p[j] = g_pool[g * DD + j] / cnt;
    __syncthreads();

    float acc = lin_b[j];
#pragma unroll
    for (int k = 0; k < 64; k++) acc += p[k] * sw[k * 65 + j];

    red[j] = acc;
    __syncthreads();
    for (int s = 32; s > 0; s >>= 1) {
        if (j < s) red[j] = fmaxf(red[j], red[j + s]);
        __syncthreads();
    }
    float mx = red[0];
    __syncthreads();
    float e = expf(acc - mx);
    red[j] = e;
    __syncthreads();
    for (int s = 32; s > 0; s >>= 1) {
        if (j < s) red[j] += red[j + s];
        __syncthreads();
    }
    out[g * DD + j] = e / red[0];
}

extern "C" void kernel_launch(void* const* d_in, const int* in_sizes, int n_in,
                              void* d_out, int out_size) {
    const float* x      = (const float*)d_in[0];
    const int*   ei     = (const int*)d_in[1];
    const int*   batch  = (const int*)d_in[2];
    const float* rel_w  = (const float*)d_in[3];
    const float* rel_b  = (const float*)d_in[4];
    const float* root_w = (const float*)d_in[5];
    const float* lin_w  = (const float*)d_in[6];
    const float* lin_b  = (const float*)d_in[7];
    float* out = (float*)d_out;

    cudaFuncSetAttribute(k_layer, cudaFuncAttributeMaxDynamicSharedMemorySize,
                         SMEM_DYN);

    const int* src = ei;
    const int* dst = ei + NE;

    k_zero<<<(NN + 255) / 256, 256>>>();
    k_count<<<(NE + 255) / 256, 256>>>(dst);
    k_scanA<<<NCHUNK, CHUNK>>>();
    k_scanB<<<NCHUNK, CHUNK>>>(batch);
    k_fill<<<(NE + 255) / 256, 256>>>(src, dst);

    int insel = 0;
    for (int l = 0; l < 5; l++) {
        int outsel = (insel == 1) ? 2 : 1;
        k_layer<<<(NN + 127) / 128, 256, SMEM_DYN>>>(
            x, insel, outsel,
            rel_w + l * DD * DD,
            root_w + l * DD * DD,
            rel_b + l * DD,
            (l >= 3) ? 1 : 0,
            (l == 4) ? 1 : 0,
            batch);
        insel = outsel;
    }

    k_final<<<GG, DD>>>(lin_w, lin_b, out);
}